// round 6
// baseline (speedup 1.0000x reference)
#include <cuda_runtime.h>

#define NN 100000
#define NE 1600000
#define NG 16
#define PERG (NE / NG)      // 100000 edges per graph segment
#define TSTEP (NN / NG)     // 6250 threshold step
#define BN_EPS 1e-5f

typedef unsigned long long u64;

// ---------------- scratch ----------------------------------------------------
__device__ float g_acc1[NN * 64];   // x + aggr1 (raw)
__device__ float g_h1[NN * 64];     // MLP1 output (post-relu, pre-BN)
__device__ float g_acc2[NN * 64];   // raw aggr of h1
__device__ float g_deg[NN];         // valid in-degree
__device__ float g_stats1[128];
__device__ float g_stats2[128];
__device__ float g_ab1[128];        // BN1 folded affine: a[64], b[64]
__device__ float g_gsum[NG * 64];
__device__ float g_cnt[NG];

// ---------------- helpers ----------------------------------------------------
__device__ __forceinline__ void red_add_v4(float4* addr, float4 v) {
    asm volatile("red.global.add.v4.f32 [%0], {%1,%2,%3,%4};"
                 :: "l"(addr), "f"(v.x), "f"(v.y), "f"(v.z), "f"(v.w)
                 : "memory");
}
__device__ __forceinline__ void red_add_f32(float* addr, float v) {
    asm volatile("red.global.add.f32 [%0], %1;" :: "l"(addr), "f"(v) : "memory");
}
__device__ __forceinline__ u64 pk2(float lo, float hi) {
    u64 r; asm("mov.b64 %0, {%1,%2};" : "=l"(r) : "f"(lo), "f"(hi)); return r;
}
__device__ __forceinline__ void upk2(u64 v, float& a, float& b) {
    asm("mov.b64 {%0,%1}, %2;" : "=f"(a), "=f"(b) : "l"(v));
}
__device__ __forceinline__ u64 ffma2(u64 a, u64 b, u64 c) {
    u64 d; asm("fma.rn.f32x2 %0, %1, %2, %3;" : "=l"(d) : "l"(a), "l"(b), "l"(c));
    return d;
}
__device__ __forceinline__ u64 add2(u64 a, u64 b) {
    u64 d; asm("add.rn.f32x2 %0, %1, %2;" : "=l"(d) : "l"(a), "l"(b));
    return d;
}
__device__ __forceinline__ u64 relu2(u64 v) {
    float a, b; upk2(v, a, b);
    return pk2(fmaxf(a, 0.f), fmaxf(b, 0.f));
}

// Table geometry: per warp, 64 rows x 18 u64 (32 nodes/row = 16 pairs, stride
// 36 floats -> conflict-free transposed stores, 16B-aligned LDS.128 reads).
#define ROW_U64 18
#define TBL_U64 (64 * ROW_U64)          // 1152 u64 per warp
#define TILE_N 32                        // nodes per warp tile
#define NTILES (NN / TILE_N)             // 3125 exact

// ---------------- small kernels ----------------------------------------------
__global__ void zero_kernel() {
    int i = blockIdx.x * blockDim.x + threadIdx.x;
    if (i < NN) g_deg[i] = 0.f;
    if (i < 128) { g_stats1[i] = 0.f; g_stats2[i] = 0.f; }
    if (i < NG * 64) g_gsum[i] = 0.f;
    if (i < NG) g_cnt[i] = 0.f;
}

__global__ void copy_init_kernel(const float4* __restrict__ x) {
    int i = blockIdx.x * blockDim.x + threadIdx.x;
    if (i < NN * 16) ((float4*)g_acc1)[i] = x[i];
}

// raw masked scatter-add. layer 0: feat=x (param), acc=g_acc1, accumulate deg.
//                         layer 1: feat=g_h1,      acc=g_acc2.
// Device-side symbol references ONLY (host cannot take __device__ addresses).
__global__ void scatter_kernel(const int* __restrict__ ei,
                               const float4* __restrict__ xfeat, int layer) {
    int idx = blockIdx.x * blockDim.x + threadIdx.x;
    int e = idx >> 4;
    if (e >= NE) return;
    int c = idx & 15;

    int th = (e / PERG) * TSTEP;
    int s = __ldg(&ei[e]);
    int d = __ldg(&ei[NE + e]);
    if (s < th || d < th) return;

    const float4* feat = (layer == 0) ? xfeat : (const float4*)g_h1;
    float4* acc = (layer == 0) ? (float4*)g_acc1 : (float4*)g_acc2;

    float4 v = __ldg(&feat[s * 16 + c]);
    red_add_v4(&acc[d * 16 + c], v);
    if (layer == 0 && c == 0) red_add_f32(&g_deg[d], 1.f);
}

// ---------------- MLP1: 64 -> relu 32 -> relu 64 ------------------------------
// Per warp-tile of 32 nodes. Also writes zeros into g_acc2 and BN1 stats.
__global__ __launch_bounds__(256) void mlp1_kernel(
    const float* __restrict__ W1a, const float* __restrict__ b1a,
    const float* __restrict__ W1b, const float* __restrict__ b1b) {
    extern __shared__ u64 sm[];
    u64* tables = sm;                          // 8 * 1152 u64
    float* sWa = (float*)(sm + 8 * TBL_U64);   // 2048 f32
    float* sWb = sWa + 2048;                   // 2048 f32

    for (int i = threadIdx.x; i < 2048; i += 256) {
        sWa[i] = W1a[i];
        sWb[i] = W1b[i];
    }
    __syncthreads();

    int lane = threadIdx.x & 31;
    u64* xs = tables + (threadIdx.x >> 5) * TBL_U64;
    float* xsf = (float*)xs;

    int warp = (blockIdx.x * 256 + threadIdx.x) >> 5;
    int nw = (gridDim.x * 256) >> 5;
    int chunk = (NTILES + nw - 1) / nw;
    int tBeg = warp * chunk;
    int tEnd = min(tBeg + chunk, NTILES);

    float bav = b1a[lane];
    u64 bA = pk2(bav, bav);
    float bl = b1b[lane], bh = b1b[lane + 32];
    u64 bbL = pk2(bl, bl), bbH = pk2(bh, bh);

    u64 sA = 0, sB = 0, qA = 0, qB = 0;

    int ln16 = lane & 15, c2 = lane >> 4;

    for (int t = tBeg; t < tEnd; t++) {
        int nb = t * TILE_N;
        // ---- stage 32 nodes transposed (conflict-free) ----
        const float4* src4 = (const float4*)g_acc1;
#pragma unroll
        for (int cc = 0; cc < 8; cc++) {
            int c = cc * 2 + c2;
#pragma unroll
            for (int h = 0; h < 2; h++) {
                int n = h * 16 + ln16;
                float4 v = src4[(nb + n) * 16 + c];
                float* p = xsf + (4 * c) * 36 + n;
                p[0] = v.x; p[36] = v.y; p[72] = v.z; p[108] = v.w;
            }
        }
        __syncwarp();

        // ---- layer a: K=64, 32 hidden (lane = hidden) ----
        u64 acc[16];
#pragma unroll
        for (int i = 0; i < 16; i++) acc[i] = bA;
#pragma unroll 2
        for (int k = 0; k < 64; k++) {
            const ulonglong2* row = (const ulonglong2*)(xs + k * ROW_U64);
            float w = sWa[k * 32 + lane];
            u64 wd = pk2(w, w);
#pragma unroll
            for (int q = 0; q < 8; q++) {
                ulonglong2 x2 = row[q];
                acc[2 * q]     = ffma2(x2.x, wd, acc[2 * q]);
                acc[2 * q + 1] = ffma2(x2.y, wd, acc[2 * q + 1]);
            }
        }
        __syncwarp();
        {
            u64* trow = xs + lane * ROW_U64;   // overwrite rows 0..31
#pragma unroll
            for (int q = 0; q < 16; q++) trow[q] = relu2(acc[q]);
        }
        __syncwarp();

        // ---- layer b: K=32, 64 out (lane = f and f+32) ----
        u64 aO[16], aP[16];
#pragma unroll
        for (int i = 0; i < 16; i++) { aO[i] = bbL; aP[i] = bbH; }
#pragma unroll 2
        for (int k = 0; k < 32; k++) {
            const ulonglong2* row = (const ulonglong2*)(xs + k * ROW_U64);
            float wl = sWb[k * 64 + lane], wh = sWb[k * 64 + lane + 32];
            u64 wld = pk2(wl, wl), whd = pk2(wh, wh);
#pragma unroll
            for (int q = 0; q < 8; q++) {
                ulonglong2 x2 = row[q];
                aO[2 * q]     = ffma2(x2.x, wld, aO[2 * q]);
                aO[2 * q + 1] = ffma2(x2.y, wld, aO[2 * q + 1]);
                aP[2 * q]     = ffma2(x2.x, whd, aP[2 * q]);
                aP[2 * q + 1] = ffma2(x2.y, whd, aP[2 * q + 1]);
            }
        }

        // ---- epilogue: relu, store h1, stats, zero acc2 ----
#pragma unroll
        for (int p = 0; p < 16; p++) {
            u64 O = relu2(aO[p]), P = relu2(aP[p]);
            float lo, hi, lo2, hi2;
            upk2(O, lo, hi); upk2(P, lo2, hi2);
            int n0 = nb + 2 * p;
            g_h1[n0 * 64 + lane] = lo;
            g_h1[(n0 + 1) * 64 + lane] = hi;
            g_h1[n0 * 64 + 32 + lane] = lo2;
            g_h1[(n0 + 1) * 64 + 32 + lane] = hi2;
            sA = add2(sA, O); qA = ffma2(O, O, qA);
            sB = add2(sB, P); qB = ffma2(P, P, qB);
        }
        float4 z = make_float4(0.f, 0.f, 0.f, 0.f);
        float4* az = (float4*)(g_acc2 + nb * 64);
#pragma unroll
        for (int i = 0; i < 16; i++) az[lane + 32 * i] = z;
        __syncwarp();
    }

    float a, b;
    upk2(sA, a, b); atomicAdd(&g_stats1[lane], a + b);
    upk2(sB, a, b); atomicAdd(&g_stats1[lane + 32], a + b);
    upk2(qA, a, b); atomicAdd(&g_stats1[64 + lane], a + b);
    upk2(qB, a, b); atomicAdd(&g_stats1[96 + lane], a + b);
}

__global__ void finalize1_kernel(const float* __restrict__ gamma,
                                 const float* __restrict__ beta) {
    int f = threadIdx.x;
    float mean = g_stats1[f] * (1.f / NN);
    float var = g_stats1[64 + f] * (1.f / NN) - mean * mean;
    float a = gamma[f] * rsqrtf(var + BN_EPS);
    g_ab1[f] = a;
    g_ab1[64 + f] = beta[f] - mean * a;
}

// ---------------- MLP2: 64 -> relu 64 -> relu 64 + stats + pooling ------------
// Input built on the fly: in = a*(h1 + S) + (1+deg)*b
__global__ __launch_bounds__(256) void mlp2_kernel(
    const float* __restrict__ W2a, const float* __restrict__ b2a,
    const float* __restrict__ W2b, const float* __restrict__ b2b,
    const int* __restrict__ batch) {
    extern __shared__ u64 sm[];
    u64* tables = sm;
    float* sWa = (float*)(sm + 8 * TBL_U64);   // 4096 f32
    float* sWb = sWa + 4096;                   // 4096 f32

    for (int i = threadIdx.x; i < 4096; i += 256) {
        sWa[i] = W2a[i];
        sWb[i] = W2b[i];
    }
    __syncthreads();

    int lane = threadIdx.x & 31;
    u64* xs = tables + (threadIdx.x >> 5) * TBL_U64;
    float* xsf = (float*)xs;

    int warp = (blockIdx.x * 256 + threadIdx.x) >> 5;
    int nw = (gridDim.x * 256) >> 5;
    int chunk = (NTILES + nw - 1) / nw;
    int tBeg = warp * chunk;
    int tEnd = min(tBeg + chunk, NTILES);

    float al = b2a[lane], ah = b2a[lane + 32];
    u64 baL = pk2(al, al), baH = pk2(ah, ah);
    float bl = b2b[lane], bh = b2b[lane + 32];
    u64 bbL = pk2(bl, bl), bbH = pk2(bh, bh);

    u64 sA = 0, sB = 0, qA = 0, qB = 0;
    u64 pA = 0, pB = 0;
    float crun = 0.f;
    int cg = -1;

    int ln16 = lane & 15, c2 = lane >> 4;

    for (int t = tBeg; t < tEnd; t++) {
        int nb = t * TILE_N;
        // ---- stage: in = a*(h1+S) + (1+deg)*b, transposed ----
        const float4* h4 = (const float4*)g_h1;
        const float4* S4 = (const float4*)g_acc2;
        const float4* ab4 = (const float4*)g_ab1;
#pragma unroll
        for (int cc = 0; cc < 8; cc++) {
            int c = cc * 2 + c2;
            float4 a4 = ab4[c];
            float4 b4 = ab4[16 + c];
#pragma unroll
            for (int h = 0; h < 2; h++) {
                int n = h * 16 + ln16;
                int gi = (nb + n) * 16 + c;
                float4 hv = h4[gi];
                float4 Sv = S4[gi];
                float dg = 1.f + g_deg[nb + n];
                float4 v;
                v.x = fmaf(dg, b4.x, a4.x * (hv.x + Sv.x));
                v.y = fmaf(dg, b4.y, a4.y * (hv.y + Sv.y));
                v.z = fmaf(dg, b4.z, a4.z * (hv.z + Sv.z));
                v.w = fmaf(dg, b4.w, a4.w * (hv.w + Sv.w));
                float* p = xsf + (4 * c) * 36 + n;
                p[0] = v.x; p[36] = v.y; p[72] = v.z; p[108] = v.w;
            }
        }
        __syncwarp();

        // ---- layer a: K=64, 64 out ----
        u64 aO[16], aP[16];
#pragma unroll
        for (int i = 0; i < 16; i++) { aO[i] = baL; aP[i] = baH; }
#pragma unroll 2
        for (int k = 0; k < 64; k++) {
            const ulonglong2* row = (const ulonglong2*)(xs + k * ROW_U64);
            float wl = sWa[k * 64 + lane], wh = sWa[k * 64 + lane + 32];
            u64 wld = pk2(wl, wl), whd = pk2(wh, wh);
#pragma unroll
            for (int q = 0; q < 8; q++) {
                ulonglong2 x2 = row[q];
                aO[2 * q]     = ffma2(x2.x, wld, aO[2 * q]);
                aO[2 * q + 1] = ffma2(x2.y, wld, aO[2 * q + 1]);
                aP[2 * q]     = ffma2(x2.x, whd, aP[2 * q]);
                aP[2 * q + 1] = ffma2(x2.y, whd, aP[2 * q + 1]);
            }
        }
        __syncwarp();
        {
            u64* r0 = xs + lane * ROW_U64;
            u64* r1 = xs + (lane + 32) * ROW_U64;
#pragma unroll
            for (int q = 0; q < 16; q++) { r0[q] = relu2(aO[q]); r1[q] = relu2(aP[q]); }
        }
        __syncwarp();

        // ---- layer b: K=64, 64 out ----
#pragma unroll
        for (int i = 0; i < 16; i++) { aO[i] = bbL; aP[i] = bbH; }
#pragma unroll 2
        for (int k = 0; k < 64; k++) {
            const ulonglong2* row = (const ulonglong2*)(xs + k * ROW_U64);
            float wl = sWb[k * 64 + lane], wh = sWb[k * 64 + lane + 32];
            u64 wld = pk2(wl, wl), whd = pk2(wh, wh);
#pragma unroll
            for (int q = 0; q < 8; q++) {
                ulonglong2 x2 = row[q];
                aO[2 * q]     = ffma2(x2.x, wld, aO[2 * q]);
                aO[2 * q + 1] = ffma2(x2.y, wld, aO[2 * q + 1]);
                aP[2 * q]     = ffma2(x2.x, whd, aP[2 * q]);
                aP[2 * q + 1] = ffma2(x2.y, whd, aP[2 * q + 1]);
            }
        }

        // ---- epilogue: relu, stats, run-length pooling (no store) ----
#pragma unroll
        for (int p = 0; p < 16; p++) {
            u64 O = relu2(aO[p]), P = relu2(aP[p]);
            sA = add2(sA, O); qA = ffma2(O, O, qA);
            sB = add2(sB, P); qB = ffma2(P, P, qB);

            int2 bp = *((const int2*)(batch + nb + 2 * p));
            if (bp.x == cg && bp.y == cg) {
                pA = add2(pA, O); pB = add2(pB, P); crun += 2.f;
            } else {
                if (cg >= 0 && crun > 0.f) {
                    float a, b;
                    upk2(pA, a, b); atomicAdd(&g_gsum[cg * 64 + lane], a + b);
                    upk2(pB, a, b); atomicAdd(&g_gsum[cg * 64 + lane + 32], a + b);
                    if (lane == 0) atomicAdd(&g_cnt[cg], crun);
                }
                if (bp.x == bp.y) {
                    cg = bp.x; pA = O; pB = P; crun = 2.f;
                } else {
                    float a, b;
                    upk2(O, a, b);
                    atomicAdd(&g_gsum[bp.x * 64 + lane], a);
                    u64 tA = pk2(0.f, b);
                    upk2(P, a, b);
                    atomicAdd(&g_gsum[bp.x * 64 + lane + 32], a);
                    if (lane == 0) atomicAdd(&g_cnt[bp.x], 1.f);
                    cg = bp.y; pA = tA; pB = pk2(0.f, b); crun = 1.f;
                }
            }
        }
        __syncwarp();
    }
    if (cg >= 0 && crun > 0.f) {
        float a, b;
        upk2(pA, a, b); atomicAdd(&g_gsum[cg * 64 + lane], a + b);
        upk2(pB, a, b); atomicAdd(&g_gsum[cg * 64 + lane + 32], a + b);
        if (lane == 0) atomicAdd(&g_cnt[cg], crun);
    }
    float a, b;
    upk2(sA, a, b); atomicAdd(&g_stats2[lane], a + b);
    upk2(sB, a, b); atomicAdd(&g_stats2[lane + 32], a + b);
    upk2(qA, a, b); atomicAdd(&g_stats2[64 + lane], a + b);
    upk2(qB, a, b); atomicAdd(&g_stats2[96 + lane], a + b);
}

__global__ void finalize2_kernel(const float* __restrict__ gamma,
                                 const float* __restrict__ beta,
                                 float* __restrict__ out) {
    int f = threadIdx.x;
    int g = blockIdx.x;
    float mean = g_stats2[f] * (1.f / NN);
    float var = g_stats2[64 + f] * (1.f / NN) - mean * mean;
    float inv = rsqrtf(var + BN_EPS);
    float cnt = fmaxf(g_cnt[g], 1.f);
    float m = g_gsum[g * 64 + f] / cnt;
    out[g * 64 + f] = (m - mean) * inv * gamma[f] + beta[f];
}

// ---------------- launch -----------------------------------------------------
extern "C" void kernel_launch(void* const* d_in, const int* in_sizes, int n_in,
                              void* d_out, int out_size) {
    const float* x = (const float*)d_in[0];
    const int* ei = (const int*)d_in[1];
    const int* batch = (const int*)d_in[2];

    int base = 3;
    while (base < n_in && in_sizes[base] == 1) base++;
    const float* W1a = (const float*)d_in[base + 0];
    const float* b1a = (const float*)d_in[base + 1];
    const float* W1b = (const float*)d_in[base + 2];
    const float* b1b = (const float*)d_in[base + 3];
    const float* g1  = (const float*)d_in[base + 4];
    const float* be1 = (const float*)d_in[base + 5];
    const float* W2a = (const float*)d_in[base + 6];
    const float* b2a = (const float*)d_in[base + 7];
    const float* W2b = (const float*)d_in[base + 8];
    const float* b2b = (const float*)d_in[base + 9];
    const float* g2  = (const float*)d_in[base + 10];
    const float* be2 = (const float*)d_in[base + 11];
    float* out = (float*)d_out;

    const int smem1 = 8 * TBL_U64 * 8 + 2 * 2048 * 4;   // 90112
    const int smem2 = 8 * TBL_U64 * 8 + 2 * 4096 * 4;   // 106496
    cudaFuncSetAttribute(mlp1_kernel, cudaFuncAttributeMaxDynamicSharedMemorySize, smem1);
    cudaFuncSetAttribute(mlp2_kernel, cudaFuncAttributeMaxDynamicSharedMemorySize, smem2);

    zero_kernel<<<(NN + 255) / 256, 256>>>();
    copy_init_kernel<<<(NN * 16 + 255) / 256, 256>>>((const float4*)x);
    scatter_kernel<<<NE / 16, 256>>>(ei, (const float4*)x, 0);
    mlp1_kernel<<<296, 256, smem1>>>(W1a, b1a, W1b, b1b);
    finalize1_kernel<<<1, 64>>>(g1, be1);
    scatter_kernel<<<NE / 16, 256>>>(ei, (const float4*)x, 1);
    mlp2_kernel<<<296, 256, smem2>>>(W2a, b2a, W2b, b2b, batch);
    finalize2_kernel<<<NG, 64>>>(g2, be2, out);
}

// round 7
// speedup vs baseline: 1.9625x; 1.9625x over previous
#include <cuda_runtime.h>

#define NN 100000
#define NE 1600000
#define NG 16
#define PERG (NE / NG)      // 100000 edges per graph segment
#define TSTEP (NN / NG)     // 6250 threshold step
#define BN_EPS 1e-5f
#define MAXDEG 64

typedef unsigned long long u64;

// ---------------- scratch ----------------------------------------------------
__device__ float g_acc1[NN * 64];   // x[d] + sum_j x[src_j]
__device__ float g_h1[NN * 64];     // MLP1 output (post-relu, pre-BN)
__device__ float g_acc2[NN * 64];   // h1[d] + sum_j h1[src_j]
__device__ int   g_adj[NN * MAXDEG];
__device__ int   g_ideg[NN];
__device__ float g_stats1[128];
__device__ float g_stats2[128];
__device__ float g_ab1[128];        // BN1 folded affine: a[64], b[64]
__device__ float g_gsum[NG * 64];
__device__ float g_cnt[NG];

// ---------------- helpers ----------------------------------------------------
__device__ __forceinline__ u64 pk2(float lo, float hi) {
    u64 r; asm("mov.b64 %0, {%1,%2};" : "=l"(r) : "f"(lo), "f"(hi)); return r;
}
__device__ __forceinline__ void upk2(u64 v, float& a, float& b) {
    asm("mov.b64 {%0,%1}, %2;" : "=f"(a), "=f"(b) : "l"(v));
}
__device__ __forceinline__ u64 ffma2(u64 a, u64 b, u64 c) {
    u64 d; asm("fma.rn.f32x2 %0, %1, %2, %3;" : "=l"(d) : "l"(a), "l"(b), "l"(c));
    return d;
}
__device__ __forceinline__ u64 add2(u64 a, u64 b) {
    u64 d; asm("add.rn.f32x2 %0, %1, %2;" : "=l"(d) : "l"(a), "l"(b));
    return d;
}
__device__ __forceinline__ u64 relu2(u64 v) {
    float a, b; upk2(v, a, b);
    return pk2(fmaxf(a, 0.f), fmaxf(b, 0.f));
}

// Table geometry: per warp, 64 rows x 10 u64 (16 nodes = 8 pairs data, stride
// 20 floats -> conflict-free transposed stores, 16B-aligned rows).
#define ROW_U64 10
#define TBL_U64 (64 * ROW_U64)          // 640 u64 per warp
#define TILE_N 16
#define NTILES (NN / TILE_N)            // 6250 exact

// ---------------- small kernels ----------------------------------------------
__global__ void zero_kernel() {
    int i = blockIdx.x * blockDim.x + threadIdx.x;
    if (i < NN) g_ideg[i] = 0;
    if (i < 128) { g_stats1[i] = 0.f; g_stats2[i] = 0.f; }
    if (i < NG * 64) g_gsum[i] = 0.f;
    if (i < NG) g_cnt[i] = 0.f;
}

// one thread per edge: append src to dst's adjacency if the edge is valid
__global__ void adj_build_kernel(const int* __restrict__ ei) {
    int e = blockIdx.x * blockDim.x + threadIdx.x;
    if (e >= NE) return;
    int th = (e / PERG) * TSTEP;
    int s = __ldg(&ei[e]);
    int d = __ldg(&ei[NE + e]);
    if (s < th || d < th) return;
    int slot = atomicAdd(&g_ideg[d], 1) & (MAXDEG - 1);
    g_adj[d * MAXDEG + slot] = s;
}

// warp per node: acc[d] = feat[d] + sum_{j in adj[d]} feat[j]
// layer 0: feat = x (param), acc = g_acc1 ; layer 1: feat = g_h1, acc = g_acc2
__global__ __launch_bounds__(256) void gather_kernel(const float* __restrict__ xfeat,
                                                     int layer) {
    int w = (blockIdx.x * 256 + threadIdx.x) >> 5;
    if (w >= NN) return;
    int lane = threadIdx.x & 31;

    const float* feat = (layer == 0) ? xfeat : (const float*)g_h1;
    float* acc = (layer == 0) ? g_acc1 : g_acc2;

    int deg = __ldg(&g_ideg[w]);
    const int* adj = g_adj + w * MAXDEG;
    const float* self = feat + w * 64;
    float a0 = __ldg(&self[lane]);
    float a1 = __ldg(&self[lane + 32]);

    int j = 0;
    for (; j + 2 <= deg; j += 2) {
        int s0 = __ldg(&adj[j]);
        int s1 = __ldg(&adj[j + 1]);
        const float* r0 = feat + s0 * 64;
        const float* r1 = feat + s1 * 64;
        float v0 = __ldg(&r0[lane]),      v1 = __ldg(&r1[lane]);
        float v2 = __ldg(&r0[lane + 32]), v3 = __ldg(&r1[lane + 32]);
        a0 += v0 + v1;
        a1 += v2 + v3;
    }
    if (j < deg) {
        int s0 = __ldg(&adj[j]);
        const float* r0 = feat + s0 * 64;
        a0 += __ldg(&r0[lane]);
        a1 += __ldg(&r0[lane + 32]);
    }
    acc[w * 64 + lane] = a0;
    acc[w * 64 + lane + 32] = a1;
}

// ---------------- MLP1: 64 -> relu 32 -> relu 64 ------------------------------
__global__ __launch_bounds__(256) void mlp1_kernel(
    const float* __restrict__ W1a, const float* __restrict__ b1a,
    const float* __restrict__ W1b, const float* __restrict__ b1b) {
    extern __shared__ u64 sm[];
    u64* tables = sm;                          // 8 * 640 u64
    float* sWa = (float*)(sm + 8 * TBL_U64);   // 2048 f32
    float* sWb = sWa + 2048;                   // 2048 f32

    for (int i = threadIdx.x; i < 2048; i += 256) {
        sWa[i] = W1a[i];
        sWb[i] = W1b[i];
    }
    __syncthreads();

    int lane = threadIdx.x & 31;
    u64* xs = tables + (threadIdx.x >> 5) * TBL_U64;
    float* xsf = (float*)xs;

    int warp = (blockIdx.x * 256 + threadIdx.x) >> 5;
    int nw = (gridDim.x * 256) >> 5;
    int chunk = (NTILES + nw - 1) / nw;
    int tBeg = warp * chunk;
    int tEnd = min(tBeg + chunk, NTILES);

    float bav = b1a[lane];
    u64 bA = pk2(bav, bav);
    float bl = b1b[lane], bh = b1b[lane + 32];
    u64 bbL = pk2(bl, bl), bbH = pk2(bh, bh);

    u64 sA = 0, sB = 0, qA = 0, qB = 0;
    int ln16 = lane & 15, c2 = lane >> 4;

    for (int t = tBeg; t < tEnd; t++) {
        int nb = t * TILE_N;
        // ---- stage 16 nodes transposed (conflict-free, stride 20 floats) ----
        const float4* src4 = (const float4*)g_acc1;
#pragma unroll
        for (int cc = 0; cc < 8; cc++) {
            int c = cc * 2 + c2;
            float4 v = src4[(nb + ln16) * 16 + c];
            float* p = xsf + (4 * c) * 20 + ln16;
            p[0] = v.x; p[20] = v.y; p[40] = v.z; p[60] = v.w;
        }
        __syncwarp();

        // ---- layer a: K=64, 32 hidden (lane = hidden) ----
        u64 acc[8];
#pragma unroll
        for (int i = 0; i < 8; i++) acc[i] = bA;
#pragma unroll 4
        for (int k = 0; k < 64; k++) {
            const ulonglong2* row = (const ulonglong2*)(xs + k * ROW_U64);
            float w = sWa[k * 32 + lane];
            u64 wd = pk2(w, w);
#pragma unroll
            for (int q = 0; q < 4; q++) {
                ulonglong2 x2 = row[q];
                acc[2 * q]     = ffma2(x2.x, wd, acc[2 * q]);
                acc[2 * q + 1] = ffma2(x2.y, wd, acc[2 * q + 1]);
            }
        }
        __syncwarp();
        {
            u64* trow = xs + lane * ROW_U64;   // rows 0..31 = hidden
#pragma unroll
            for (int q = 0; q < 8; q++) trow[q] = relu2(acc[q]);
        }
        __syncwarp();

        // ---- layer b: K=32, 64 out (lane = f and f+32) ----
        u64 aO[8], aP[8];
#pragma unroll
        for (int i = 0; i < 8; i++) { aO[i] = bbL; aP[i] = bbH; }
#pragma unroll 4
        for (int k = 0; k < 32; k++) {
            const ulonglong2* row = (const ulonglong2*)(xs + k * ROW_U64);
            float wl = sWb[k * 64 + lane], wh = sWb[k * 64 + lane + 32];
            u64 wld = pk2(wl, wl), whd = pk2(wh, wh);
#pragma unroll
            for (int q = 0; q < 4; q++) {
                ulonglong2 x2 = row[q];
                aO[2 * q]     = ffma2(x2.x, wld, aO[2 * q]);
                aO[2 * q + 1] = ffma2(x2.y, wld, aO[2 * q + 1]);
                aP[2 * q]     = ffma2(x2.x, whd, aP[2 * q]);
                aP[2 * q + 1] = ffma2(x2.y, whd, aP[2 * q + 1]);
            }
        }

        // ---- epilogue: relu, store h1, stats ----
#pragma unroll
        for (int p = 0; p < 8; p++) {
            u64 O = relu2(aO[p]), P = relu2(aP[p]);
            float lo, hi, lo2, hi2;
            upk2(O, lo, hi); upk2(P, lo2, hi2);
            int n0 = nb + 2 * p;
            g_h1[n0 * 64 + lane] = lo;
            g_h1[(n0 + 1) * 64 + lane] = hi;
            g_h1[n0 * 64 + 32 + lane] = lo2;
            g_h1[(n0 + 1) * 64 + 32 + lane] = hi2;
            sA = add2(sA, O); qA = ffma2(O, O, qA);
            sB = add2(sB, P); qB = ffma2(P, P, qB);
        }
        __syncwarp();
    }

    float a, b;
    upk2(sA, a, b); atomicAdd(&g_stats1[lane], a + b);
    upk2(sB, a, b); atomicAdd(&g_stats1[lane + 32], a + b);
    upk2(qA, a, b); atomicAdd(&g_stats1[64 + lane], a + b);
    upk2(qB, a, b); atomicAdd(&g_stats1[96 + lane], a + b);
}

__global__ void finalize1_kernel(const float* __restrict__ gamma,
                                 const float* __restrict__ beta) {
    int f = threadIdx.x;
    float mean = g_stats1[f] * (1.f / NN);
    float var = g_stats1[64 + f] * (1.f / NN) - mean * mean;
    float a = gamma[f] * rsqrtf(var + BN_EPS);
    g_ab1[f] = a;
    g_ab1[64 + f] = beta[f] - mean * a;
}

// ---------------- MLP2: 64 -> relu 64 -> relu 64 + stats + pooling ------------
// Input built on the fly: in = a*T + (1+deg)*b, where T = h1[d] + sum h1[src]
__global__ __launch_bounds__(256) void mlp2_kernel(
    const float* __restrict__ W2a, const float* __restrict__ b2a,
    const float* __restrict__ W2b, const float* __restrict__ b2b,
    const int* __restrict__ batch) {
    extern __shared__ u64 sm[];
    u64* tables = sm;
    float* sWa = (float*)(sm + 8 * TBL_U64);   // 4096 f32
    float* sWb = sWa + 4096;                   // 4096 f32

    for (int i = threadIdx.x; i < 4096; i += 256) {
        sWa[i] = W2a[i];
        sWb[i] = W2b[i];
    }
    __syncthreads();

    int lane = threadIdx.x & 31;
    u64* xs = tables + (threadIdx.x >> 5) * TBL_U64;
    float* xsf = (float*)xs;

    int warp = (blockIdx.x * 256 + threadIdx.x) >> 5;
    int nw = (gridDim.x * 256) >> 5;
    int chunk = (NTILES + nw - 1) / nw;
    int tBeg = warp * chunk;
    int tEnd = min(tBeg + chunk, NTILES);

    float al = b2a[lane], ah = b2a[lane + 32];
    u64 baL = pk2(al, al), baH = pk2(ah, ah);
    float bl = b2b[lane], bh = b2b[lane + 32];
    u64 bbL = pk2(bl, bl), bbH = pk2(bh, bh);

    u64 sA = 0, sB = 0, qA = 0, qB = 0;
    u64 pA = 0, pB = 0;
    float crun = 0.f;
    int cg = -1;
    int ln16 = lane & 15, c2 = lane >> 4;

    for (int t = tBeg; t < tEnd; t++) {
        int nb = t * TILE_N;
        // ---- stage: in = a*T + (1+deg)*b, transposed ----
        const float4* T4 = (const float4*)g_acc2;
        const float4* ab4 = (const float4*)g_ab1;
        float dg = 1.f + (float)__ldg(&g_ideg[nb + ln16]);
#pragma unroll
        for (int cc = 0; cc < 8; cc++) {
            int c = cc * 2 + c2;
            float4 a4 = ab4[c];
            float4 b4 = ab4[16 + c];
            float4 Tv = T4[(nb + ln16) * 16 + c];
            float4 v;
            v.x = fmaf(dg, b4.x, a4.x * Tv.x);
            v.y = fmaf(dg, b4.y, a4.y * Tv.y);
            v.z = fmaf(dg, b4.z, a4.z * Tv.z);
            v.w = fmaf(dg, b4.w, a4.w * Tv.w);
            float* p = xsf + (4 * c) * 20 + ln16;
            p[0] = v.x; p[20] = v.y; p[40] = v.z; p[60] = v.w;
        }
        __syncwarp();

        // ---- layer a: K=64, 64 out ----
        u64 aO[8], aP[8];
#pragma unroll
        for (int i = 0; i < 8; i++) { aO[i] = baL; aP[i] = baH; }
#pragma unroll 4
        for (int k = 0; k < 64; k++) {
            const ulonglong2* row = (const ulonglong2*)(xs + k * ROW_U64);
            float wl = sWa[k * 64 + lane], wh = sWa[k * 64 + lane + 32];
            u64 wld = pk2(wl, wl), whd = pk2(wh, wh);
#pragma unroll
            for (int q = 0; q < 4; q++) {
                ulonglong2 x2 = row[q];
                aO[2 * q]     = ffma2(x2.x, wld, aO[2 * q]);
                aO[2 * q + 1] = ffma2(x2.y, wld, aO[2 * q + 1]);
                aP[2 * q]     = ffma2(x2.x, whd, aP[2 * q]);
                aP[2 * q + 1] = ffma2(x2.y, whd, aP[2 * q + 1]);
            }
        }
        __syncwarp();
        {
            u64* r0 = xs + lane * ROW_U64;
            u64* r1 = xs + (lane + 32) * ROW_U64;
#pragma unroll
            for (int q = 0; q < 8; q++) { r0[q] = relu2(aO[q]); r1[q] = relu2(aP[q]); }
        }
        __syncwarp();

        // ---- layer b: K=64, 64 out ----
#pragma unroll
        for (int i = 0; i < 8; i++) { aO[i] = bbL; aP[i] = bbH; }
#pragma unroll 4
        for (int k = 0; k < 64; k++) {
            const ulonglong2* row = (const ulonglong2*)(xs + k * ROW_U64);
            float wl = sWb[k * 64 + lane], wh = sWb[k * 64 + lane + 32];
            u64 wld = pk2(wl, wl), whd = pk2(wh, wh);
#pragma unroll
            for (int q = 0; q < 4; q++) {
                ulonglong2 x2 = row[q];
                aO[2 * q]     = ffma2(x2.x, wld, aO[2 * q]);
                aO[2 * q + 1] = ffma2(x2.y, wld, aO[2 * q + 1]);
                aP[2 * q]     = ffma2(x2.x, whd, aP[2 * q]);
                aP[2 * q + 1] = ffma2(x2.y, whd, aP[2 * q + 1]);
            }
        }

        // ---- epilogue: relu, stats, run-length pooling (no store) ----
#pragma unroll
        for (int p = 0; p < 8; p++) {
            u64 O = relu2(aO[p]), P = relu2(aP[p]);
            sA = add2(sA, O); qA = ffma2(O, O, qA);
            sB = add2(sB, P); qB = ffma2(P, P, qB);

            int2 bp = *((const int2*)(batch + nb + 2 * p));
            if (bp.x == cg && bp.y == cg) {
                pA = add2(pA, O); pB = add2(pB, P); crun += 2.f;
            } else {
                if (cg >= 0 && crun > 0.f) {
                    float a, b;
                    upk2(pA, a, b); atomicAdd(&g_gsum[cg * 64 + lane], a + b);
                    upk2(pB, a, b); atomicAdd(&g_gsum[cg * 64 + lane + 32], a + b);
                    if (lane == 0) atomicAdd(&g_cnt[cg], crun);
                }
                if (bp.x == bp.y) {
                    cg = bp.x; pA = O; pB = P; crun = 2.f;
                } else {
                    float a, b;
                    upk2(O, a, b);
                    atomicAdd(&g_gsum[bp.x * 64 + lane], a);
                    u64 tA = pk2(0.f, b);
                    upk2(P, a, b);
                    atomicAdd(&g_gsum[bp.x * 64 + lane + 32], a);
                    if (lane == 0) atomicAdd(&g_cnt[bp.x], 1.f);
                    cg = bp.y; pA = tA; pB = pk2(0.f, b); crun = 1.f;
                }
            }
        }
        __syncwarp();
    }
    if (cg >= 0 && crun > 0.f) {
        float a, b;
        upk2(pA, a, b); atomicAdd(&g_gsum[cg * 64 + lane], a + b);
        upk2(pB, a, b); atomicAdd(&g_gsum[cg * 64 + lane + 32], a + b);
        if (lane == 0) atomicAdd(&g_cnt[cg], crun);
    }
    float a, b;
    upk2(sA, a, b); atomicAdd(&g_stats2[lane], a + b);
    upk2(sB, a, b); atomicAdd(&g_stats2[lane + 32], a + b);
    upk2(qA, a, b); atomicAdd(&g_stats2[64 + lane], a + b);
    upk2(qB, a, b); atomicAdd(&g_stats2[96 + lane], a + b);
}

__global__ void finalize2_kernel(const float* __restrict__ gamma,
                                 const float* __restrict__ beta,
                                 float* __restrict__ out) {
    int f = threadIdx.x;
    int g = blockIdx.x;
    float mean = g_stats2[f] * (1.f / NN);
    float var = g_stats2[64 + f] * (1.f / NN) - mean * mean;
    float inv = rsqrtf(var + BN_EPS);
    float cnt = fmaxf(g_cnt[g], 1.f);
    float m = g_gsum[g * 64 + f] / cnt;
    out[g * 64 + f] = (m - mean) * inv * gamma[f] + beta[f];
}

// ---------------- launch -----------------------------------------------------
extern "C" void kernel_launch(void* const* d_in, const int* in_sizes, int n_in,
                              void* d_out, int out_size) {
    const float* x = (const float*)d_in[0];
    const int* ei = (const int*)d_in[1];
    const int* batch = (const int*)d_in[2];

    int base = 3;
    while (base < n_in && in_sizes[base] == 1) base++;
    const float* W1a = (const float*)d_in[base + 0];
    const float* b1a = (const float*)d_in[base + 1];
    const float* W1b = (const float*)d_in[base + 2];
    const float* b1b = (const float*)d_in[base + 3];
    const float* g1  = (const float*)d_in[base + 4];
    const float* be1 = (const float*)d_in[base + 5];
    const float* W2a = (const float*)d_in[base + 6];
    const float* b2a = (const float*)d_in[base + 7];
    const float* W2b = (const float*)d_in[base + 8];
    const float* b2b = (const float*)d_in[base + 9];
    const float* g2  = (const float*)d_in[base + 10];
    const float* be2 = (const float*)d_in[base + 11];
    float* out = (float*)d_out;

    const int smem1 = 8 * TBL_U64 * 8 + 2 * 2048 * 4;   // 40960 + 16384 = 57344
    const int smem2 = 8 * TBL_U64 * 8 + 2 * 4096 * 4;   // 40960 + 32768 = 73728
    cudaFuncSetAttribute(mlp1_kernel, cudaFuncAttributeMaxDynamicSharedMemorySize, smem1);
    cudaFuncSetAttribute(mlp2_kernel, cudaFuncAttributeMaxDynamicSharedMemorySize, smem2);

    zero_kernel<<<(NN + 255) / 256, 256>>>();
    adj_build_kernel<<<NE / 256, 256>>>(ei);
    gather_kernel<<<(NN * 32 + 255) / 256, 256>>>(x, 0);
    mlp1_kernel<<<391, 256, smem1>>>(W1a, b1a, W1b, b1b);
    finalize1_kernel<<<1, 64>>>(g1, be1);
    gather_kernel<<<(NN * 32 + 255) / 256, 256>>>(x, 1);
    mlp2_kernel<<<391, 256, smem2>>>(W2a, b2a, W2b, b2b, batch);
    finalize2_kernel<<<NG, 64>>>(g2, be2, out);
}

// round 9
// speedup vs baseline: 2.1800x; 1.1108x over previous
#include <cuda_runtime.h>

#define NN 100000
#define NE 1600000
#define NG 16
#define PERG (NE / NG)      // 100000 edges per graph segment
#define TSTEP (NN / NG)     // 6250 threshold step
#define BN_EPS 1e-5f
#define MAXDEG 64

typedef unsigned long long u64;

// ---------------- scratch ----------------------------------------------------
__device__ float g_h1[NN * 64];     // MLP1 output (post-relu, pre-BN)
__device__ int   g_adj[NN * MAXDEG];
__device__ int   g_ideg[NN];
__device__ float g_stats1[128];
__device__ float g_stats2[128];
__device__ float g_ab1[128];        // BN1 folded affine: a[64], b[64]
__device__ float g_gsum[NG * 64];
__device__ float g_cnt[NG];

// ---------------- helpers ----------------------------------------------------
__device__ __forceinline__ u64 pk2(float lo, float hi) {
    u64 r; asm("mov.b64 %0, {%1,%2};" : "=l"(r) : "f"(lo), "f"(hi)); return r;
}
__device__ __forceinline__ void upk2(u64 v, float& a, float& b) {
    asm("mov.b64 {%0,%1}, %2;" : "=f"(a), "=f"(b) : "l"(v));
}
__device__ __forceinline__ u64 ffma2(u64 a, u64 b, u64 c) {
    u64 d; asm("fma.rn.f32x2 %0, %1, %2, %3;" : "=l"(d) : "l"(a), "l"(b), "l"(c));
    return d;
}
__device__ __forceinline__ u64 add2(u64 a, u64 b) {
    u64 d; asm("add.rn.f32x2 %0, %1, %2;" : "=l"(d) : "l"(a), "l"(b));
    return d;
}
__device__ __forceinline__ u64 relu2(u64 v) {
    float a, b; upk2(v, a, b);
    return pk2(fmaxf(a, 0.f), fmaxf(b, 0.f));
}

// Table: per warp, 64 rows x 10 u64 (16 nodes = 8 pairs, stride 20 floats).
#define ROW_U64 10
#define TBL_U64 (64 * ROW_U64)          // 640 u64 per warp
#define TILE_N 16
#define NTILES (NN / TILE_N)            // 6250 exact

// ---------------- small kernels ----------------------------------------------
__global__ void zero_kernel() {
    int i = blockIdx.x * blockDim.x + threadIdx.x;
    if (i < NN) g_ideg[i] = 0;
    if (i < 128) { g_stats1[i] = 0.f; g_stats2[i] = 0.f; }
    if (i < NG * 64) g_gsum[i] = 0.f;
    if (i < NG) g_cnt[i] = 0.f;
}

__global__ void adj_build_kernel(const int* __restrict__ ei) {
    int e = blockIdx.x * blockDim.x + threadIdx.x;
    if (e >= NE) return;
    int th = (e / PERG) * TSTEP;
    int s = __ldg(&ei[e]);
    int d = __ldg(&ei[NE + e]);
    if (s < th || d < th) return;
    int slot = atomicAdd(&g_ideg[d], 1) & (MAXDEG - 1);
    g_adj[d * MAXDEG + slot] = s;
}

// ---------------- MLP1 (fused gather): 64 -> relu 32 -> relu 64 --------------
__global__ __launch_bounds__(256, 3) void mlp1_kernel(
    const float* __restrict__ xfeat,
    const float* __restrict__ W1a, const float* __restrict__ b1a,
    const float* __restrict__ W1b, const float* __restrict__ b1b) {
    extern __shared__ u64 sm[];
    u64* tables = sm;                          // 8 * 640 u64
    float* sWa = (float*)(sm + 8 * TBL_U64);   // 2048 f32
    float* sWb = sWa + 2048;                   // 2048 f32

    for (int i = threadIdx.x; i < 2048; i += 256) {
        sWa[i] = W1a[i];
        sWb[i] = W1b[i];
    }
    __syncthreads();

    int lane = threadIdx.x & 31;
    u64* xs = tables + (threadIdx.x >> 5) * TBL_U64;
    float* xsf = (float*)xs;

    int warp = (blockIdx.x * 256 + threadIdx.x) >> 5;
    int nw = (gridDim.x * 256) >> 5;

    float bav = b1a[lane];
    u64 bA = pk2(bav, bav);
    float bl = b1b[lane], bh = b1b[lane + 32];
    u64 bbL = pk2(bl, bl), bbH = pk2(bh, bh);

    u64 sA = 0, sB = 0, qA = 0, qB = 0;

    for (int t = warp; t < NTILES; t += nw) {
        int nb = t * TILE_N;
        // ---- fused gather: x[d] + sum x[src], transposed store ----
#pragma unroll 1
        for (int n = 0; n < TILE_N; n++) {
            int node = nb + n;
            int deg = __ldg(&g_ideg[node]);
            const int* adj = g_adj + node * MAXDEG;
            const float* self = xfeat + node * 64;
            float a0 = __ldg(&self[lane]);
            float a1 = __ldg(&self[lane + 32]);
            int j = 0;
            for (; j + 2 <= deg; j += 2) {
                int s0 = __ldg(&adj[j]), s1 = __ldg(&adj[j + 1]);
                const float* r0 = xfeat + s0 * 64;
                const float* r1 = xfeat + s1 * 64;
                float v0 = __ldg(&r0[lane]),      v1 = __ldg(&r1[lane]);
                float v2 = __ldg(&r0[lane + 32]), v3 = __ldg(&r1[lane + 32]);
                a0 += v0 + v1;
                a1 += v2 + v3;
            }
            if (j < deg) {
                const float* r0 = xfeat + __ldg(&adj[j]) * 64;
                a0 += __ldg(&r0[lane]);
                a1 += __ldg(&r0[lane + 32]);
            }
            xsf[lane * 20 + n] = a0;
            xsf[(lane + 32) * 20 + n] = a1;
        }
        __syncwarp();

        // ---- layer a: K=64, 32 hidden (lane = hidden) ----
        u64 acc[8];
#pragma unroll
        for (int i = 0; i < 8; i++) acc[i] = bA;
#pragma unroll 4
        for (int k = 0; k < 64; k++) {
            const ulonglong2* row = (const ulonglong2*)(xs + k * ROW_U64);
            float w = sWa[k * 32 + lane];
            u64 wd = pk2(w, w);
#pragma unroll
            for (int q = 0; q < 4; q++) {
                ulonglong2 x2 = row[q];
                acc[2 * q]     = ffma2(x2.x, wd, acc[2 * q]);
                acc[2 * q + 1] = ffma2(x2.y, wd, acc[2 * q + 1]);
            }
        }
        __syncwarp();
        {
            u64* trow = xs + lane * ROW_U64;   // rows 0..31 = hidden
#pragma unroll
            for (int q = 0; q < 8; q++) trow[q] = relu2(acc[q]);
        }
        __syncwarp();

        // ---- layer b: K=32, 64 out ----
        u64 aO[8], aP[8];
#pragma unroll
        for (int i = 0; i < 8; i++) { aO[i] = bbL; aP[i] = bbH; }
#pragma unroll 4
        for (int k = 0; k < 32; k++) {
            const ulonglong2* row = (const ulonglong2*)(xs + k * ROW_U64);
            float wl = sWb[k * 64 + lane], wh = sWb[k * 64 + lane + 32];
            u64 wld = pk2(wl, wl), whd = pk2(wh, wh);
#pragma unroll
            for (int q = 0; q < 4; q++) {
                ulonglong2 x2 = row[q];
                aO[2 * q]     = ffma2(x2.x, wld, aO[2 * q]);
                aO[2 * q + 1] = ffma2(x2.y, wld, aO[2 * q + 1]);
                aP[2 * q]     = ffma2(x2.x, whd, aP[2 * q]);
                aP[2 * q + 1] = ffma2(x2.y, whd, aP[2 * q + 1]);
            }
        }

        // ---- epilogue: relu, store h1, stats ----
#pragma unroll
        for (int p = 0; p < 8; p++) {
            u64 O = relu2(aO[p]), P = relu2(aP[p]);
            float lo, hi, lo2, hi2;
            upk2(O, lo, hi); upk2(P, lo2, hi2);
            int n0 = nb + 2 * p;
            g_h1[n0 * 64 + lane] = lo;
            g_h1[(n0 + 1) * 64 + lane] = hi;
            g_h1[n0 * 64 + 32 + lane] = lo2;
            g_h1[(n0 + 1) * 64 + 32 + lane] = hi2;
            sA = add2(sA, O); qA = ffma2(O, O, qA);
            sB = add2(sB, P); qB = ffma2(P, P, qB);
        }
        __syncwarp();
    }

    float a, b;
    upk2(sA, a, b); atomicAdd(&g_stats1[lane], a + b);
    upk2(sB, a, b); atomicAdd(&g_stats1[lane + 32], a + b);
    upk2(qA, a, b); atomicAdd(&g_stats1[64 + lane], a + b);
    upk2(qB, a, b); atomicAdd(&g_stats1[96 + lane], a + b);
}

__global__ void finalize1_kernel(const float* __restrict__ gamma,
                                 const float* __restrict__ beta) {
    int f = threadIdx.x;
    float mean = g_stats1[f] * (1.f / NN);
    float var = g_stats1[64 + f] * (1.f / NN) - mean * mean;
    float a = gamma[f] * rsqrtf(var + BN_EPS);
    g_ab1[f] = a;
    g_ab1[64 + f] = beta[f] - mean * a;
}

// ---------------- MLP2 (fused gather): 64 -> relu 64 -> relu 64 + pooling ----
// in = a*(h1[d] + sum h1[src]) + (1+deg)*b
__global__ __launch_bounds__(256, 3) void mlp2_kernel(
    const float* __restrict__ W2a, const float* __restrict__ b2a,
    const float* __restrict__ W2b, const float* __restrict__ b2b,
    const int* __restrict__ batch) {
    extern __shared__ u64 sm[];
    u64* tables = sm;
    float* sWa = (float*)(sm + 8 * TBL_U64);   // 4096 f32
    float* sWb = sWa + 4096;                   // 4096 f32

    for (int i = threadIdx.x; i < 4096; i += 256) {
        sWa[i] = W2a[i];
        sWb[i] = W2b[i];
    }
    __syncthreads();

    int lane = threadIdx.x & 31;
    u64* xs = tables + (threadIdx.x >> 5) * TBL_U64;
    float* xsf = (float*)xs;

    int warp = (blockIdx.x * 256 + threadIdx.x) >> 5;
    int nw = (gridDim.x * 256) >> 5;

    float aLo = g_ab1[lane], aHi = g_ab1[lane + 32];
    float bLo = g_ab1[64 + lane], bHi = g_ab1[96 + lane];

    float al = b2a[lane], ah = b2a[lane + 32];
    u64 baL = pk2(al, al), baH = pk2(ah, ah);
    float bl = b2b[lane], bh = b2b[lane + 32];
    u64 bbL = pk2(bl, bl), bbH = pk2(bh, bh);

    u64 sA = 0, sB = 0, qA = 0, qB = 0;
    u64 pA = 0, pB = 0;
    float crun = 0.f;
    int cg = -1;

    for (int t = warp; t < NTILES; t += nw) {
        int nb = t * TILE_N;
        // ---- fused gather over h1 + BN1 affine, transposed store ----
        const float* feat = (const float*)g_h1;
#pragma unroll 1
        for (int n = 0; n < TILE_N; n++) {
            int node = nb + n;
            int deg = __ldg(&g_ideg[node]);
            const int* adj = g_adj + node * MAXDEG;
            const float* self = feat + node * 64;
            float a0 = __ldg(&self[lane]);
            float a1 = __ldg(&self[lane + 32]);
            int j = 0;
            for (; j + 2 <= deg; j += 2) {
                int s0 = __ldg(&adj[j]), s1 = __ldg(&adj[j + 1]);
                const float* r0 = feat + s0 * 64;
                const float* r1 = feat + s1 * 64;
                float v0 = __ldg(&r0[lane]),      v1 = __ldg(&r1[lane]);
                float v2 = __ldg(&r0[lane + 32]), v3 = __ldg(&r1[lane + 32]);
                a0 += v0 + v1;
                a1 += v2 + v3;
            }
            if (j < deg) {
                const float* r0 = feat + __ldg(&adj[j]) * 64;
                a0 += __ldg(&r0[lane]);
                a1 += __ldg(&r0[lane + 32]);
            }
            float dg = 1.f + (float)deg;
            xsf[lane * 20 + n] = fmaf(dg, bLo, aLo * a0);
            xsf[(lane + 32) * 20 + n] = fmaf(dg, bHi, aHi * a1);
        }
        __syncwarp();

        // ---- layer a: K=64, 64 out ----
        u64 aO[8], aP[8];
#pragma unroll
        for (int i = 0; i < 8; i++) { aO[i] = baL; aP[i] = baH; }
#pragma unroll 4
        for (int k = 0; k < 64; k++) {
            const ulonglong2* row = (const ulonglong2*)(xs + k * ROW_U64);
            float wl = sWa[k * 64 + lane], wh = sWa[k * 64 + lane + 32];
            u64 wld = pk2(wl, wl), whd = pk2(wh, wh);
#pragma unroll
            for (int q = 0; q < 4; q++) {
                ulonglong2 x2 = row[q];
                aO[2 * q]     = ffma2(x2.x, wld, aO[2 * q]);
                aO[2 * q + 1] = ffma2(x2.y, wld, aO[2 * q + 1]);
                aP[2 * q]     = ffma2(x2.x, whd, aP[2 * q]);
                aP[2 * q + 1] = ffma2(x2.y, whd, aP[2 * q + 1]);
            }
        }
        __syncwarp();
        {
            u64* r0 = xs + lane * ROW_U64;
            u64* r1 = xs + (lane + 32) * ROW_U64;
#pragma unroll
            for (int q = 0; q < 8; q++) { r0[q] = relu2(aO[q]); r1[q] = relu2(aP[q]); }
        }
        __syncwarp();

        // ---- layer b: K=64, 64 out ----
#pragma unroll
        for (int i = 0; i < 8; i++) { aO[i] = bbL; aP[i] = bbH; }
#pragma unroll 4
        for (int k = 0; k < 64; k++) {
            const ulonglong2* row = (const ulonglong2*)(xs + k * ROW_U64);
            float wl = sWb[k * 64 + lane], wh = sWb[k * 64 + lane + 32];
            u64 wld = pk2(wl, wl), whd = pk2(wh, wh);
#pragma unroll
            for (int q = 0; q < 4; q++) {
                ulonglong2 x2 = row[q];
                aO[2 * q]     = ffma2(x2.x, wld, aO[2 * q]);
                aO[2 * q + 1] = ffma2(x2.y, wld, aO[2 * q + 1]);
                aP[2 * q]     = ffma2(x2.x, whd, aP[2 * q]);
                aP[2 * q + 1] = ffma2(x2.y, whd, aP[2 * q + 1]);
            }
        }

        // ---- epilogue: relu, stats, run-length pooling ----
#pragma unroll
        for (int p = 0; p < 8; p++) {
            u64 O = relu2(aO[p]), P = relu2(aP[p]);
            sA = add2(sA, O); qA = ffma2(O, O, qA);
            sB = add2(sB, P); qB = ffma2(P, P, qB);

            int2 bp = *((const int2*)(batch + nb + 2 * p));
            if (bp.x == cg && bp.y == cg) {
                pA = add2(pA, O); pB = add2(pB, P); crun += 2.f;
            } else {
                if (cg >= 0 && crun > 0.f) {
                    float a, b;
                    upk2(pA, a, b); atomicAdd(&g_gsum[cg * 64 + lane], a + b);
                    upk2(pB, a, b); atomicAdd(&g_gsum[cg * 64 + lane + 32], a + b);
                    if (lane == 0) atomicAdd(&g_cnt[cg], crun);
                }
                if (bp.x == bp.y) {
                    cg = bp.x; pA = O; pB = P; crun = 2.f;
                } else {
                    float a, b;
                    upk2(O, a, b);
                    atomicAdd(&g_gsum[bp.x * 64 + lane], a);
                    u64 tA = pk2(0.f, b);
                    upk2(P, a, b);
                    atomicAdd(&g_gsum[bp.x * 64 + lane + 32], a);
                    if (lane == 0) atomicAdd(&g_cnt[bp.x], 1.f);
                    cg = bp.y; pA = tA; pB = pk2(0.f, b); crun = 1.f;
                }
            }
        }
        __syncwarp();
    }
    if (cg >= 0 && crun > 0.f) {
        float a, b;
        upk2(pA, a, b); atomicAdd(&g_gsum[cg * 64 + lane], a + b);
        upk2(pB, a, b); atomicAdd(&g_gsum[cg * 64 + lane + 32], a + b);
        if (lane == 0) atomicAdd(&g_cnt[cg], crun);
    }
    float a, b;
    upk2(sA, a, b); atomicAdd(&g_stats2[lane], a + b);
    upk2(sB, a, b); atomicAdd(&g_stats2[lane + 32], a + b);
    upk2(qA, a, b); atomicAdd(&g_stats2[64 + lane], a + b);
    upk2(qB, a, b); atomicAdd(&g_stats2[96 + lane], a + b);
}

__global__ void finalize2_kernel(const float* __restrict__ gamma,
                                 const float* __restrict__ beta,
                                 float* __restrict__ out) {
    int f = threadIdx.x;
    int g = blockIdx.x;
    float mean = g_stats2[f] * (1.f / NN);
    float var = g_stats2[64 + f] * (1.f / NN) - mean * mean;
    float inv = rsqrtf(var + BN_EPS);
    float cnt = fmaxf(g_cnt[g], 1.f);
    float m = g_gsum[g * 64 + f] / cnt;
    out[g * 64 + f] = (m - mean) * inv * gamma[f] + beta[f];
}

// ---------------- launch -----------------------------------------------------
extern "C" void kernel_launch(void* const* d_in, const int* in_sizes, int n_in,
                              void* d_out, int out_size) {
    const float* x = (const float*)d_in[0];
    const int* ei = (const int*)d_in[1];
    const int* batch = (const int*)d_in[2];

    int base = 3;
    while (base < n_in && in_sizes[base] == 1) base++;
    const float* W1a = (const float*)d_in[base + 0];
    const float* b1a = (const float*)d_in[base + 1];
    const float* W1b = (const float*)d_in[base + 2];
    const float* b1b = (const float*)d_in[base + 3];
    const float* g1  = (const float*)d_in[base + 4];
    const float* be1 = (const float*)d_in[base + 5];
    const float* W2a = (const float*)d_in[base + 6];
    const float* b2a = (const float*)d_in[base + 7];
    const float* W2b = (const float*)d_in[base + 8];
    const float* b2b = (const float*)d_in[base + 9];
    const float* g2  = (const float*)d_in[base + 10];
    const float* be2 = (const float*)d_in[base + 11];
    float* out = (float*)d_out;

    const int smem1 = 8 * TBL_U64 * 8 + 2 * 2048 * 4;   // 57344
    const int smem2 = 8 * TBL_U64 * 8 + 2 * 4096 * 4;   // 73728
    cudaFuncSetAttribute(mlp1_kernel, cudaFuncAttributeMaxDynamicSharedMemorySize, smem1);
    cudaFuncSetAttribute(mlp2_kernel, cudaFuncAttributeMaxDynamicSharedMemorySize, smem2);

    zero_kernel<<<(NN + 255) / 256, 256>>>();
    adj_build_kernel<<<NE / 256, 256>>>(ei);
    mlp1_kernel<<<444, 256, smem1>>>(x, W1a, b1a, W1b, b1b);
    finalize1_kernel<<<1, 64>>>(g1, be1);
    mlp2_kernel<<<444, 256, smem2>>>(W2a, b2a, W2b, b2b, batch);
    finalize2_kernel<<<NG, 64>>>(g2, be2, out);
}